// round 7
// baseline (speedup 1.0000x reference)
#include <cuda_runtime.h>

// Problem constants (shapes are fixed for this problem instance)
#define NMAX   16000
#define NGRAPH 32
#define NBUMP  32
#define NDIR   64
#define NHID   256
#define NCLS   10

// Scratch (device globals: allocation-free per harness rules)
static __device__ float g_nh[NMAX * NDIR];              // node heights [N][64]
static __device__ float g_diff[NGRAPH * NBUMP * NDIR];  // signed ECC delta accumulator
static __device__ float g_hid[NGRAPH * NHID];           // MLP hidden layer

__device__ __forceinline__ float rcpa(float x) {
    float r;
    asm("rcp.approx.f32 %0, %1;" : "=f"(r) : "f"(x));
    return r;
}

// Scatter the monotone sigmoid staircase of one (item, dir) as a difference
// array into base[b*64], b in [0,32). sigmoid(A + b*B) with A = -100*(1+h),
// B = 200/31. Only |z| < T band needs evaluation; below -> 0, above -> 1.
__device__ __forceinline__ void ecc_scatter(float h, float* base, float sgn) {
    const float Bc    = 6.4516129032f;      // 200/31
    const float invB  = 0.155f;             // 31/200
    const float T     = 16.0f;
    const float invEB = 1.0f / 633.72363f;  // exp(-200/31)

    float A = fmaf(h, -100.0f, -100.0f);    // -100*(1+h)
    if (A < -T - 31.0f * Bc) return;        // whole curve ~0: nothing to add

    int b0 = (int)ceilf((-T - A) * invB);  if (b0 < 0)  b0 = 0;
    int b1 = (int)floorf((T - A) * invB);  if (b1 > 31) b1 = 31;

    float sprev = 0.0f;
    if (b1 >= b0) {
        // q = exp(-z) at b0; advance by multiplying exp(-B) per step
        float q = __expf(-fmaf((float)b0, Bc, A));
        #pragma unroll 1
        for (int b = b0; b <= b1; ++b) {
            float s = rcpa(1.0f + q);       // sigmoid(z) = 1/(1+e^-z)
            atomicAdd(base + (b << 6), sgn * (s - sprev));
            sprev = s;
            q *= invEB;
        }
    }
    // closing step to the all-ones tail (also handles curve == all-ones)
    int bx = (b1 >= b0) ? (b1 + 1) : b0;
    if (bx <= 31) atomicAdd(base + (bx << 6), sgn * (1.0f - sprev));
}

__global__ void k_zero() {
    g_diff[blockIdx.x * 256 + threadIdx.x] = 0.0f;
}

__global__ void k_nh(const float* __restrict__ x, const float* __restrict__ nw,
                     const float* __restrict__ v, int N) {
    int idx = blockIdx.x * blockDim.x + threadIdx.x;
    if (idx >= N * NDIR) return;
    int n = idx >> 6, d = idx & 63;
    float w = nw[n];
    float h = w * (x[3 * n]     * v[d] +
                   x[3 * n + 1] * v[NDIR + d] +
                   x[3 * n + 2] * v[2 * NDIR + d]);
    g_nh[idx] = h;
}

__global__ void k_ecc_node(const int* __restrict__ bid, int N) {
    int idx = blockIdx.x * blockDim.x + threadIdx.x;
    if (idx >= N * NDIR) return;
    int n = idx >> 6, d = idx & 63;
    int g = bid[n];
    ecc_scatter(g_nh[idx], &g_diff[(g << 11) + d], 1.0f);
}

__global__ void k_ecc_edge(const float* __restrict__ ew, const int* __restrict__ ei,
                           const int* __restrict__ bid, int E) {
    int idx = blockIdx.x * blockDim.x + threadIdx.x;
    if (idx >= E * NDIR) return;
    int e = idx >> 6, d = idx & 63;
    int a = ei[e], b = ei[E + e];
    float h = fmaxf(g_nh[(a << 6) + d], g_nh[(b << 6) + d]) * ew[e];
    int g = bid[a];
    ecc_scatter(h, &g_diff[(g << 11) + d], -1.0f);
}

__global__ void k_ecc_face(const float* __restrict__ fw, const int* __restrict__ fc,
                           const int* __restrict__ bid, int F) {
    int idx = blockIdx.x * blockDim.x + threadIdx.x;
    if (idx >= F * NDIR) return;
    int f = idx >> 6, d = idx & 63;
    int a = fc[f], b = fc[F + f], c = fc[2 * F + f];
    float h = fmaxf(fmaxf(g_nh[(a << 6) + d], g_nh[(b << 6) + d]),
                    g_nh[(c << 6) + d]) * fw[f];
    int g = bid[a];
    ecc_scatter(h, &g_diff[(g << 11) + d], 1.0f);
}

// Prefix-sum deltas over b -> flat[g][b*64+d]
__global__ void k_prefix(float* __restrict__ flat) {
    int idx = blockIdx.x * 256 + threadIdx.x;   // 0..2047 : (g, d)
    int g = idx >> 6, d = idx & 63;
    const float* src = &g_diff[(g << 11) + d];
    float* dst = flat + (g << 11) + d;
    float s = 0.0f;
    #pragma unroll
    for (int b = 0; b < NBUMP; ++b) {
        s += src[b << 6];
        dst[b << 6] = s;
    }
}

// hidden = relu(flat @ W1.T + b1): one warp per (g, hid), float4 dot of 2048
__global__ void k_hidden(const float* __restrict__ flat, const float* __restrict__ W1,
                         const float* __restrict__ b1) {
    int t = blockIdx.x * blockDim.x + threadIdx.x;
    int warp = t >> 5, lane = t & 31;           // 8192 warps total
    int g = warp >> 8, hid = warp & 255;
    const float4* fr = (const float4*)(flat + (g << 11));
    const float4* wr = (const float4*)(W1 + hid * 2048);
    float s = 0.0f;
    #pragma unroll
    for (int k = lane; k < 512; k += 32) {
        float4 a = fr[k], w = wr[k];
        s += a.x * w.x + a.y * w.y + a.z * w.z + a.w * w.w;
    }
    #pragma unroll
    for (int o = 16; o; o >>= 1) s += __shfl_xor_sync(0xffffffffu, s, o);
    if (lane == 0) g_hid[(g << 8) + hid] = fmaxf(s + b1[hid], 0.0f);
}

// logits = hidden @ W2.T + b2: one warp per (g, class)
__global__ void k_logits(const float* __restrict__ W2, const float* __restrict__ b2,
                         float* __restrict__ out) {
    int t = blockIdx.x * blockDim.x + threadIdx.x;
    int warp = t >> 5, lane = t & 31;
    if (warp >= NGRAPH * NCLS) return;
    int g = warp / NCLS, c = warp - g * NCLS;
    const float* hr = g_hid + (g << 8);
    const float* wr = W2 + (c << 8);
    float s = 0.0f;
    #pragma unroll
    for (int k = lane; k < NHID; k += 32) s += hr[k] * wr[k];
    #pragma unroll
    for (int o = 16; o; o >>= 1) s += __shfl_xor_sync(0xffffffffu, s, o);
    if (lane == 0) out[g * NCLS + c] = s + b2[c];
}

extern "C" void kernel_launch(void* const* d_in, const int* in_sizes, int n_in,
                              void* d_out, int out_size) {
    const float* x  = (const float*)d_in[0];
    const float* nw = (const float*)d_in[1];
    const float* ew = (const float*)d_in[2];
    const float* fw = (const float*)d_in[3];
    const float* v  = (const float*)d_in[4];
    const float* W1 = (const float*)d_in[5];
    const float* b1 = (const float*)d_in[6];
    const float* W2 = (const float*)d_in[7];
    const float* b2 = (const float*)d_in[8];
    const int*   ei = (const int*)d_in[9];   // edge_index [2,E] (int32: jax x64 off)
    const int*   fc = (const int*)d_in[10];  // face [3,F]
    const int*   bid= (const int*)d_in[11];  // batch_ids [N]

    int N = in_sizes[1];   // node_weights count
    int E = in_sizes[2];   // edge_weights count
    int F = in_sizes[3];   // face_weights count

    float* out  = (float*)d_out;           // [0, 320): logits
    float* flat = out + NGRAPH * NCLS;     // [320, 320+65536): flat ECC

    k_zero<<<(NGRAPH * NBUMP * NDIR) / 256, 256>>>();
    k_nh<<<(N * NDIR + 255) / 256, 256>>>(x, nw, v, N);
    k_ecc_node<<<(N * NDIR + 255) / 256, 256>>>(bid, N);
    k_ecc_edge<<<(E * NDIR + 255) / 256, 256>>>(ew, ei, bid, E);
    k_ecc_face<<<(F * NDIR + 255) / 256, 256>>>(fw, fc, bid, F);
    k_prefix<<<8, 256>>>(flat);
    k_hidden<<<1024, 256>>>(flat, W1, b1);
    k_logits<<<(NGRAPH * NCLS * 32 + 255) / 256, 256>>>(W2, b2, out);
}

// round 9
// speedup vs baseline: 2.1567x; 2.1567x over previous
#include <cuda_runtime.h>

// Problem constants (shapes are fixed for this problem instance)
#define NMAX   16000
#define NGRAPH 32
#define NBUMP  32
#define NDIR   64
#define NHID   256
#define NCLS   10

// Scratch (device globals: allocation-free per harness rules)
static __device__ float g_nh[NMAX * NDIR];              // node heights [N][64]
static __device__ float g_diff[NGRAPH * NDIR * NBUMP];  // delta accum, layout [g][d][b]
static __device__ float g_hid[NGRAPH * NHID];           // MLP hidden layer

__device__ __forceinline__ float rcpa(float x) {
    float r;
    asm("rcp.approx.f32 %0, %1;" : "=f"(r) : "f"(x));
    return r;
}

__device__ __forceinline__ void red4(float* p, float a, float b, float c, float d) {
    asm volatile("red.global.add.v4.f32 [%0], {%1,%2,%3,%4};"
                 :: "l"(p), "f"(a), "f"(b), "f"(c), "f"(d) : "memory");
}

// Scatter the monotone sigmoid staircase of one (item, dir) as a difference
// array into base[b], b in [0,32), b contiguous. sigmoid(A + b*B) with
// A = -100*(1+h), B = 200/31. Band |z| < T evaluated; the "closing to 1" step
// emerges naturally because s saturates within e^-T inside the 8-slot window.
// Window = 8 slots from the 4-aligned base below b0 -> at most two v4 REDs.
__device__ __forceinline__ void ecc_scatter(float h, float* base, float sgn) {
    const float Bc    = 6.4516129032f;      // 200/31
    const float invB  = 0.155f;             // 31/200
    const float T     = 12.0f;
    const float invEB = 0.00157827970f;     // exp(-200/31)

    float A = fmaf(h, -100.0f, -100.0f);    // z(b) = A + b*Bc
    if (A < -T - 31.0f * Bc) return;        // whole curve ~0: nothing to add

    int b0 = (int)ceilf((-T - A) * invB);  if (b0 < 0)  b0 = 0; if (b0 > 31) b0 = 31;
    int b1 = (int)floorf((T - A) * invB);  if (b1 > 31) b1 = 31;
    int w0 = b0 & ~3;                       // 16B-aligned window start

    // Evaluate sigmoid at all 8 window slots via e^{-z} recurrence.
    // q <= e^{T + 3B} ~ e^31.4: no overflow; underflow to 0 -> s = 1 (correct).
    float q = __expf(-fmaf((float)w0, Bc, A));
    float v[8];
    float sprev = 0.0f;
    #pragma unroll
    for (int k = 0; k < 8; ++k) {
        float s = rcpa(1.0f + q);           // sigmoid = 1/(1+e^-z)
        v[k] = (s - sprev) * sgn;
        sprev = s;
        q *= invEB;
    }

    float* p = base + w0;
    red4(p, v[0], v[1], v[2], v[3]);
    // Second quad only if the staircase (incl. closing step at b1+1) reaches
    // slot >= 4 AND it stays inside the 32-bin slab (w0 <= 27).
    if ((b1 + 1 - w0 >= 4) && (w0 + 4 <= 31 - 3))
        red4(p + 4, v[4], v[5], v[6], v[7]);
}

__global__ void k_zero() {
    g_diff[blockIdx.x * 256 + threadIdx.x] = 0.0f;
}

// Fused: node heights + node ECC scatter
__global__ void k_nh_node(const float* __restrict__ x, const float* __restrict__ nw,
                          const float* __restrict__ v, const int* __restrict__ bid,
                          int N) {
    int idx = blockIdx.x * blockDim.x + threadIdx.x;
    if (idx >= N * NDIR) return;
    int n = idx >> 6, d = idx & 63;
    float w = nw[n];
    float h = w * (x[3 * n]     * v[d] +
                   x[3 * n + 1] * v[NDIR + d] +
                   x[3 * n + 2] * v[2 * NDIR + d]);
    g_nh[idx] = h;
    int g = bid[n];
    ecc_scatter(h, &g_diff[(g << 11) + (d << 5)], 1.0f);
}

__global__ void k_ecc_edge(const float* __restrict__ ew, const int* __restrict__ ei,
                           const int* __restrict__ bid, int E) {
    int idx = blockIdx.x * blockDim.x + threadIdx.x;
    if (idx >= E * NDIR) return;
    int e = idx >> 6, d = idx & 63;
    int a = ei[e], b = ei[E + e];
    float h = fmaxf(g_nh[(a << 6) + d], g_nh[(b << 6) + d]) * ew[e];
    int g = bid[a];
    ecc_scatter(h, &g_diff[(g << 11) + (d << 5)], -1.0f);
}

__global__ void k_ecc_face(const float* __restrict__ fw, const int* __restrict__ fc,
                           const int* __restrict__ bid, int F) {
    int idx = blockIdx.x * blockDim.x + threadIdx.x;
    if (idx >= F * NDIR) return;
    int f = idx >> 6, d = idx & 63;
    int a = fc[f], b = fc[F + f], c = fc[2 * F + f];
    float h = fmaxf(fmaxf(g_nh[(a << 6) + d], g_nh[(b << 6) + d]),
                    g_nh[(c << 6) + d]) * fw[f];
    int g = bid[a];
    ecc_scatter(h, &g_diff[(g << 11) + (d << 5)], 1.0f);
}

// Prefix-sum deltas over b: g_diff[g][d][b] -> flat[g][b*64+d]
__global__ void k_prefix(float* __restrict__ flat) {
    int idx = blockIdx.x * 256 + threadIdx.x;   // 0..2047 : (g, d)
    int g = idx >> 6, d = idx & 63;
    const float* src = &g_diff[(g << 11) + (d << 5)];
    float* dst = flat + (g << 11) + d;
    float s = 0.0f;
    #pragma unroll
    for (int b = 0; b < NBUMP; ++b) {
        s += src[b];
        dst[b << 6] = s;
    }
}

// hidden = relu(flat @ W1.T + b1): one warp per (g, hid), float4 dot of 2048
__global__ void k_hidden(const float* __restrict__ flat, const float* __restrict__ W1,
                         const float* __restrict__ b1) {
    int t = blockIdx.x * blockDim.x + threadIdx.x;
    int warp = t >> 5, lane = t & 31;           // 8192 warps total
    int g = warp >> 8, hid = warp & 255;
    const float4* fr = (const float4*)(flat + (g << 11));
    const float4* wr = (const float4*)(W1 + hid * 2048);
    float s = 0.0f;
    #pragma unroll
    for (int k = lane; k < 512; k += 32) {
        float4 a = fr[k], w = wr[k];
        s += a.x * w.x + a.y * w.y + a.z * w.z + a.w * w.w;
    }
    #pragma unroll
    for (int o = 16; o; o >>= 1) s += __shfl_xor_sync(0xffffffffu, s, o);
    if (lane == 0) g_hid[(g << 8) + hid] = fmaxf(s + b1[hid], 0.0f);
}

// logits = hidden @ W2.T + b2: one warp per (g, class)
__global__ void k_logits(const float* __restrict__ W2, const float* __restrict__ b2,
                         float* __restrict__ out) {
    int t = blockIdx.x * blockDim.x + threadIdx.x;
    int warp = t >> 5, lane = t & 31;
    if (warp >= NGRAPH * NCLS) return;
    int g = warp / NCLS, c = warp - g * NCLS;
    const float* hr = g_hid + (g << 8);
    const float* wr = W2 + (c << 8);
    float s = 0.0f;
    #pragma unroll
    for (int k = lane; k < NHID; k += 32) s += hr[k] * wr[k];
    #pragma unroll
    for (int o = 16; o; o >>= 1) s += __shfl_xor_sync(0xffffffffu, s, o);
    if (lane == 0) out[g * NCLS + c] = s + b2[c];
}

extern "C" void kernel_launch(void* const* d_in, const int* in_sizes, int n_in,
                              void* d_out, int out_size) {
    const float* x  = (const float*)d_in[0];
    const float* nw = (const float*)d_in[1];
    const float* ew = (const float*)d_in[2];
    const float* fw = (const float*)d_in[3];
    const float* v  = (const float*)d_in[4];
    const float* W1 = (const float*)d_in[5];
    const float* b1 = (const float*)d_in[6];
    const float* W2 = (const float*)d_in[7];
    const float* b2 = (const float*)d_in[8];
    const int*   ei = (const int*)d_in[9];   // edge_index [2,E] (int32)
    const int*   fc = (const int*)d_in[10];  // face [3,F]
    const int*   bid= (const int*)d_in[11];  // batch_ids [N]

    int N = in_sizes[1];   // node_weights count
    int E = in_sizes[2];   // edge_weights count
    int F = in_sizes[3];   // face_weights count

    float* out  = (float*)d_out;           // [0, 320): logits
    float* flat = out + NGRAPH * NCLS;     // [320, 320+65536): flat ECC

    k_zero<<<(NGRAPH * NBUMP * NDIR) / 256, 256>>>();
    k_nh_node<<<(N * NDIR + 255) / 256, 256>>>(x, nw, v, bid, N);
    k_ecc_edge<<<(E * NDIR + 255) / 256, 256>>>(ew, ei, bid, E);
    k_ecc_face<<<(F * NDIR + 255) / 256, 256>>>(fw, fc, bid, F);
    k_prefix<<<8, 256>>>(flat);
    k_hidden<<<1024, 256>>>(flat, W1, b1);
    k_logits<<<(NGRAPH * NCLS * 32 + 255) / 256, 256>>>(W2, b2, out);
}